// round 3
// baseline (speedup 1.0000x reference)
#include <cuda_runtime.h>
#include <cuda_bf16.h>
#include <cstdint>

#define ED   128
#define AD   64
#define SROWS 100        // s-rows per CTA (2 CTAs per batch)
#define THREADS 256
#define ROWB 272u        // padded row stride (136 bf16) -> conflict-free frags

// ---- shared memory layout (bytes) ----
#define A_HI_OFF 0u          // 128 rows x 272 B = 34816
#define A_LO_OFF 34816u
#define W_HI_OFF 69632u      // 64 rows x 272 B = 17408
#define W_LO_OFF 87040u
#define T_OFF    104448u     // 128 f32
#define C_OFF    104960u     // 64 f32
#define W2_OFF   105216u     // 64 f32
#define WARR_OFF 105472u     // 128 f32
#define PART_OFF 105984u     // 256 float2
#define B2_OFF   108032u
#define SMEM_BYTES 108048u

static __device__ __forceinline__ void mma16816(
    float c[4], const uint32_t a[4], uint32_t b0, uint32_t b1)
{
    asm volatile(
        "mma.sync.aligned.m16n8k16.row.col.f32.bf16.bf16.f32 "
        "{%0,%1,%2,%3}, {%4,%5,%6,%7}, {%8,%9}, {%0,%1,%2,%3};"
        : "+f"(c[0]), "+f"(c[1]), "+f"(c[2]), "+f"(c[3])
        : "r"(a[0]), "r"(a[1]), "r"(a[2]), "r"(a[3]), "r"(b0), "r"(b1));
}

__global__ void zero_out_kernel(float* out, int n)
{
    int i = blockIdx.x * blockDim.x + threadIdx.x;
    if (i < n) out[i] = 0.f;
}

__global__ void __launch_bounds__(THREADS, 2)
attn_din_kernel(const float* __restrict__ behav,
                const float* __restrict__ target,
                const float* __restrict__ W1,
                const float* __restrict__ b1,
                const float* __restrict__ W2,
                const float* __restrict__ b2,
                float* __restrict__ out)
{
    extern __shared__ char smem[];
    const int tid  = threadIdx.x;
    const int wid  = tid >> 5;
    const int lane = tid & 31;
    const int b    = blockIdx.x >> 1;      // batch
    const int half = blockIdx.x & 1;       // which 100-row half

    float* tS  = (float*)(smem + T_OFF);
    float* cS  = (float*)(smem + C_OFF);
    float* w2S = (float*)(smem + W2_OFF);
    float* wAr = (float*)(smem + WARR_OFF);

    // ---- stage small vectors ----
    if (tid < ED) tS[tid]  = target[(size_t)b * ED + tid];
    if (tid < AD) w2S[tid] = W2[tid];
    if (tid == 0) *((float*)(smem + B2_OFF)) = b2[0];

    // ---- stage behaviors rows [half*100, half*100+100): hi/lo bf16 split ----
    {
        const float4* bp = (const float4*)(behav
            + ((size_t)b * 200 + (size_t)half * SROWS) * ED);
        for (int r = wid; r < SROWS; r += 8) {
            float4 v = bp[r * (ED / 4) + lane];
            __nv_bfloat162 h01 = __floats2bfloat162_rn(v.x, v.y);
            __nv_bfloat162 h23 = __floats2bfloat162_rn(v.z, v.w);
            float2 f01 = __bfloat1622float2(h01);
            float2 f23 = __bfloat1622float2(h23);
            __nv_bfloat162 l01 = __floats2bfloat162_rn(v.x - f01.x, v.y - f01.y);
            __nv_bfloat162 l23 = __floats2bfloat162_rn(v.z - f23.x, v.w - f23.y);
            uint32_t off = (uint32_t)r * ROWB + (uint32_t)lane * 8u;
            *reinterpret_cast<uint2*>(smem + A_HI_OFF + off) =
                make_uint2(*(uint32_t*)&h01, *(uint32_t*)&h23);
            *reinterpret_cast<uint2*>(smem + A_LO_OFF + off) =
                make_uint2(*(uint32_t*)&l01, *(uint32_t*)&l23);
        }
        // zero-pad rows 100..127
        for (int idx = tid; idx < 28 * 32; idx += THREADS) {
            int r = SROWS + (idx >> 5);
            uint32_t off = (uint32_t)r * ROWB + (uint32_t)(idx & 31) * 8u;
            *reinterpret_cast<uint2*>(smem + A_HI_OFF + off) = make_uint2(0u, 0u);
            *reinterpret_cast<uint2*>(smem + A_LO_OFF + off) = make_uint2(0u, 0u);
        }
    }
    __syncthreads();   // tS ready

    // ---- build per-batch weight W_b[a][k] = Wx + Wd + t[k]*Wm (hi/lo) ----
    for (int idx = tid; idx < ED * AD; idx += THREADS) {
        int k = idx >> 6, a = idx & 63;
        float w = W1[k * AD + a] + W1[(384 + k) * AD + a] + tS[k] * W1[(256 + k) * AD + a];
        __nv_bfloat16 hi = __float2bfloat16(w);
        __nv_bfloat16 lo = __float2bfloat16(w - __bfloat162float(hi));
        uint32_t off = (uint32_t)a * ROWB + (uint32_t)k * 2u;
        *reinterpret_cast<__nv_bfloat16*>(smem + W_HI_OFF + off) = hi;
        *reinterpret_cast<__nv_bfloat16*>(smem + W_LO_OFF + off) = lo;
    }

    // ---- c[a] partials: c = b1 + t @ (W_t - W_d), 4 k-quadrants ----
    {
        int a = tid & 63, q = tid >> 6;
        float acc = 0.f;
        for (int kk = 0; kk < 32; kk++) {
            int k = q * 32 + kk;
            acc += tS[k] * (W1[(128 + k) * AD + a] - W1[(384 + k) * AD + a]);
        }
        ((float*)(smem + PART_OFF))[q * 64 + a] = acc;
    }
    __syncthreads();   // A, W_b, c-partials ready

    if (tid < AD) {
        const float* p = (const float*)(smem + PART_OFF);
        cS[tid] = b1[tid] + p[tid] + p[64 + tid] + p[128 + tid] + p[192 + tid];
    }

    // ---- GEMM: warp w -> rows [16w, 16w+16) x [64]; 3 passes hi*hi, lo*hi, hi*lo ----
    float acc[8][4];
#pragma unroll
    for (int n = 0; n < 8; n++)
#pragma unroll
        for (int i = 0; i < 4; i++) acc[n][i] = 0.f;

    {
        const int g  = lane >> 2;
        const int t2 = (lane & 3) * 2;
#pragma unroll
        for (int pass = 0; pass < 3; pass++) {
            const char* Ap = smem + ((pass == 1) ? A_LO_OFF : A_HI_OFF);
            const char* Wp = smem + ((pass == 2) ? W_LO_OFF : W_HI_OFF);
#pragma unroll
            for (int ks = 0; ks < 8; ks++) {
                const uint32_t kb = (uint32_t)(ks * 16 + t2) * 2u;
                const char* base = Ap + (uint32_t)(wid * 16 + g) * ROWB + kb;
                uint32_t a[4];
                a[0] = *(const uint32_t*)(base);
                a[1] = *(const uint32_t*)(base + 8 * ROWB);
                a[2] = *(const uint32_t*)(base + 16);
                a[3] = *(const uint32_t*)(base + 8 * ROWB + 16);
#pragma unroll
                for (int n = 0; n < 8; n++) {
                    const char* wb = Wp + (uint32_t)(n * 8 + g) * ROWB + kb;
                    uint32_t b0  = *(const uint32_t*)(wb);
                    uint32_t b1r = *(const uint32_t*)(wb + 16);
                    mma16816(acc[n], a, b0, b1r);
                }
            }
        }
    }
    __syncthreads();   // cS visible to all

    // ---- epilogue: z[row] = b2 + sum_a relu(h)*W2 ; w = sigmoid(z) ----
    {
        const int g  = lane >> 2;
        const int t2 = (lane & 3) * 2;
        const float b2v = *((const float*)(smem + B2_OFF));
#pragma unroll
        for (int h = 0; h < 2; h++) {
            float z = 0.f;
#pragma unroll
            for (int n = 0; n < 8; n++) {
                int col = n * 8 + t2;
                float h0 = fmaxf(acc[n][2 * h]     + cS[col],     0.f);
                float h1 = fmaxf(acc[n][2 * h + 1] + cS[col + 1], 0.f);
                z = fmaf(h0, w2S[col], z);
                z = fmaf(h1, w2S[col + 1], z);
            }
            z += __shfl_xor_sync(0xFFFFFFFFu, z, 1);
            z += __shfl_xor_sync(0xFFFFFFFFu, z, 2);
            int s = wid * 16 + h * 8 + g;
            if ((lane & 3) == 0) {
                float wgt = (s < SROWS) ? (1.f / (1.f + __expf(-(z + b2v)))) : 0.f;
                wAr[s] = wgt;
            }
        }
    }
    __syncthreads();   // wAr ready

    // ---- weighted partial: part[e] = sum_{s in this half} w[s]*x[s][e] ----
    {
        int e2 = tid & 63, q = tid >> 6;
        float ax = 0.f, ay = 0.f;
        for (int i = 0; i < 25; i++) {
            int s = q * 25 + i;
            uint32_t off = (uint32_t)s * ROWB + (uint32_t)e2 * 4u;
            __nv_bfloat162 h2 = *reinterpret_cast<const __nv_bfloat162*>(smem + A_HI_OFF + off);
            __nv_bfloat162 l2 = *reinterpret_cast<const __nv_bfloat162*>(smem + A_LO_OFF + off);
            float2 fh = __bfloat1622float2(h2);
            float2 fl = __bfloat1622float2(l2);
            float ws = wAr[s];
            ax = fmaf(ws, fh.x + fl.x, ax);
            ay = fmaf(ws, fh.y + fl.y, ay);
        }
        ((float2*)(smem + PART_OFF))[q * 64 + e2] = make_float2(ax, ay);
    }
    __syncthreads();

    if (tid < 64) {
        const float2* p = (const float2*)(smem + PART_OFF);
        float2 r0 = p[tid], r1 = p[64 + tid], r2 = p[128 + tid], r3 = p[192 + tid];
        float ox = r0.x + r1.x + r2.x + r3.x;
        float oy = r0.y + r1.y + r2.y + r3.y;
        atomicAdd(out + (size_t)b * ED + tid * 2,     ox);
        atomicAdd(out + (size_t)b * ED + tid * 2 + 1, oy);
    }
}

extern "C" void kernel_launch(void* const* d_in, const int* in_sizes, int n_in,
                              void* d_out, int out_size)
{
    const float* behav  = (const float*)d_in[0];
    const float* target = (const float*)d_in[1];
    const float* W1     = (const float*)d_in[2];
    const float* b1     = (const float*)d_in[3];
    const float* W2     = (const float*)d_in[4];
    const float* b2     = (const float*)d_in[5];
    float* out = (float*)d_out;

    const int B = in_sizes[1] / ED;   // 2048

    static bool attr_set = false;
    if (!attr_set) {
        cudaFuncSetAttribute(attn_din_kernel,
                             cudaFuncAttributeMaxDynamicSharedMemorySize, (int)SMEM_BYTES);
        attr_set = true;
    }

    zero_out_kernel<<<(out_size + 511) / 512, 512>>>(out, out_size);
    attn_din_kernel<<<B * 2, THREADS, SMEM_BYTES>>>(behav, target, W1, b1, W2, b2, out);
}

// round 4
// speedup vs baseline: 1.4184x; 1.4184x over previous
#include <cuda_runtime.h>
#include <cuda_bf16.h>
#include <cstdint>

#define ED   128
#define AD   64
#define THREADS 256
#define ROWB 272u        // padded row stride (136 bf16) -> conflict-free frags

// ---- shared memory layout (bytes) ----
#define A_HI_OFF 0u          // 128 rows x 272 B = 34816
#define A_LO_OFF 34816u
#define W_HI_OFF 69632u      // 64 rows x 272 B = 17408
#define W_LO_OFF 87040u
#define T_OFF    104448u     // 128 f32
#define C_OFF    104960u     // 64 f32
#define W2_OFF   105216u     // 64 f32
#define WARR_OFF 105472u     // 128 f32
#define PART_OFF 105984u     // 256 float2
#define B2_OFF   108032u
#define SMEM_BYTES 108048u

static __device__ __forceinline__ void mma16816(
    float c[4], const uint32_t a[4], uint32_t b0, uint32_t b1)
{
    asm volatile(
        "mma.sync.aligned.m16n8k16.row.col.f32.bf16.bf16.f32 "
        "{%0,%1,%2,%3}, {%4,%5,%6,%7}, {%8,%9}, {%0,%1,%2,%3};"
        : "+f"(c[0]), "+f"(c[1]), "+f"(c[2]), "+f"(c[3])
        : "r"(a[0]), "r"(a[1]), "r"(a[2]), "r"(a[3]), "r"(b0), "r"(b1));
}

__global__ void __launch_bounds__(THREADS, 2)
attn_din_kernel(const float* __restrict__ behav,
                const float* __restrict__ target,
                const float* __restrict__ W1,
                const float* __restrict__ b1,
                const float* __restrict__ W2,
                const float* __restrict__ b2,
                float* __restrict__ out)
{
    extern __shared__ char smem[];
    const int tid  = threadIdx.x;
    const int wid  = tid >> 5;
    const int lane = tid & 31;
    const int b    = blockIdx.x;

    float* tS  = (float*)(smem + T_OFF);
    float* cS  = (float*)(smem + C_OFF);
    float* w2S = (float*)(smem + W2_OFF);
    float* wAr = (float*)(smem + WARR_OFF);

    // ---- stage small vectors ----
    if (tid < ED) tS[tid]  = target[(size_t)b * ED + tid];
    if (tid < AD) w2S[tid] = W2[tid];
    if (tid == 0) *((float*)(smem + B2_OFF)) = b2[0];
    __syncthreads();   // tS ready

    // ---- build per-batch weight W_b[a][k] = Wx + Wd + t[k]*Wm (hi/lo), once ----
    for (int idx = tid; idx < ED * AD; idx += THREADS) {
        int k = idx >> 6, a = idx & 63;
        float w = W1[k * AD + a] + W1[(384 + k) * AD + a] + tS[k] * W1[(256 + k) * AD + a];
        __nv_bfloat16 hi = __float2bfloat16(w);
        __nv_bfloat16 lo = __float2bfloat16(w - __bfloat162float(hi));
        uint32_t off = (uint32_t)a * ROWB + (uint32_t)k * 2u;
        *reinterpret_cast<__nv_bfloat16*>(smem + W_HI_OFF + off) = hi;
        *reinterpret_cast<__nv_bfloat16*>(smem + W_LO_OFF + off) = lo;
    }

    // ---- c[a] partials: c = b1 + t @ (W_t - W_d), 4 k-quadrants ----
    {
        int a = tid & 63, q = tid >> 6;
        float acc = 0.f;
        for (int kk = 0; kk < 32; kk++) {
            int k = q * 32 + kk;
            acc += tS[k] * (W1[(128 + k) * AD + a] - W1[(384 + k) * AD + a]);
        }
        ((float*)(smem + PART_OFF))[q * 64 + a] = acc;
    }
    __syncthreads();

    if (tid < AD) {
        const float* p = (const float*)(smem + PART_OFF);
        cS[tid] = b1[tid] + p[tid] + p[64 + tid] + p[128 + tid] + p[192 + tid];
    }
    // NOTE: cS consumed only after the next __syncthreads (inside half loop).

    const int g  = lane >> 2;          // fragment row/col group
    const int t2 = (lane & 3) * 2;     // k sub-offset

    float wax = 0.f, way = 0.f;        // persistent weighted-sum accumulators
    const int e2 = tid & 63, q = tid >> 6;

    for (int half = 0; half < 2; half++) {
        const int rows_real = half ? 72 : 128;

        // ---- stage A rows: hi/lo bf16 split (no zero padding; guards mask stale) ----
        {
            const float4* bp = (const float4*)(behav
                + ((size_t)b * 200 + (size_t)half * 128) * ED);
            for (int r = wid; r < rows_real; r += 8) {
                float4 v = bp[r * (ED / 4) + lane];
                __nv_bfloat162 h01 = __floats2bfloat162_rn(v.x, v.y);
                __nv_bfloat162 h23 = __floats2bfloat162_rn(v.z, v.w);
                float2 f01 = __bfloat1622float2(h01);
                float2 f23 = __bfloat1622float2(h23);
                __nv_bfloat162 l01 = __floats2bfloat162_rn(v.x - f01.x, v.y - f01.y);
                __nv_bfloat162 l23 = __floats2bfloat162_rn(v.z - f23.x, v.w - f23.y);
                uint32_t off = (uint32_t)r * ROWB + (uint32_t)lane * 8u;
                *reinterpret_cast<uint2*>(smem + A_HI_OFF + off) =
                    make_uint2(*(uint32_t*)&h01, *(uint32_t*)&h23);
                *reinterpret_cast<uint2*>(smem + A_LO_OFF + off) =
                    make_uint2(*(uint32_t*)&l01, *(uint32_t*)&l23);
            }
        }
        __syncthreads();   // A ready (and cS on half 0)

        // ---- GEMM: warp w -> rows [16w,16w+16) x [64]; passes hi*hi, lo*hi, hi*lo ----
        float acc[8][4];
#pragma unroll
        for (int n = 0; n < 8; n++)
#pragma unroll
            for (int i = 0; i < 4; i++) acc[n][i] = 0.f;

        if (wid * 16 < rows_real) {
#pragma unroll
            for (int pass = 0; pass < 3; pass++) {
                const char* Ap = smem + ((pass == 1) ? A_LO_OFF : A_HI_OFF);
                const char* Wp = smem + ((pass == 2) ? W_LO_OFF : W_HI_OFF);
#pragma unroll
                for (int ks = 0; ks < 8; ks++) {
                    const uint32_t kb = (uint32_t)(ks * 16 + t2) * 2u;
                    const char* base = Ap + (uint32_t)(wid * 16 + g) * ROWB + kb;
                    uint32_t a[4];
                    a[0] = *(const uint32_t*)(base);
                    a[1] = *(const uint32_t*)(base + 8 * ROWB);
                    a[2] = *(const uint32_t*)(base + 16);
                    a[3] = *(const uint32_t*)(base + 8 * ROWB + 16);
#pragma unroll
                    for (int n = 0; n < 8; n++) {
                        const char* wb = Wp + (uint32_t)(n * 8 + g) * ROWB + kb;
                        uint32_t b0  = *(const uint32_t*)(wb);
                        uint32_t b1r = *(const uint32_t*)(wb + 16);
                        mma16816(acc[n], a, b0, b1r);
                    }
                }
            }
        }

        // ---- epilogue: z = b2 + sum_a relu(D+c)*W2 ; wAr = sigmoid(z) (0 if padded) ----
        {
            const float b2v = *((const float*)(smem + B2_OFF));
#pragma unroll
            for (int h = 0; h < 2; h++) {
                float z = 0.f;
#pragma unroll
                for (int n = 0; n < 8; n++) {
                    int col = n * 8 + t2;
                    float h0 = fmaxf(acc[n][2 * h]     + cS[col],     0.f);
                    float h1 = fmaxf(acc[n][2 * h + 1] + cS[col + 1], 0.f);
                    z = fmaf(h0, w2S[col], z);
                    z = fmaf(h1, w2S[col + 1], z);
                }
                z += __shfl_xor_sync(0xFFFFFFFFu, z, 1);
                z += __shfl_xor_sync(0xFFFFFFFFu, z, 2);
                int s = wid * 16 + h * 8 + g;
                if ((lane & 3) == 0) {
                    float wgt = (s < rows_real) ? (1.f / (1.f + __expf(-(z + b2v)))) : 0.f;
                    wAr[s] = wgt;
                }
            }
        }
        __syncthreads();   // wAr ready

        // ---- weighted partial: accumulate w[s]*x[s][e] into registers ----
#pragma unroll 4
        for (int i = 0; i < 32; i++) {
            int s = q * 32 + i;
            uint32_t off = (uint32_t)s * ROWB + (uint32_t)e2 * 4u;
            __nv_bfloat162 h2 = *reinterpret_cast<const __nv_bfloat162*>(smem + A_HI_OFF + off);
            __nv_bfloat162 l2 = *reinterpret_cast<const __nv_bfloat162*>(smem + A_LO_OFF + off);
            float2 fh = __bfloat1622float2(h2);
            float2 fl = __bfloat1622float2(l2);
            float ws = wAr[s];
            wax = fmaf(ws, fh.x + fl.x, wax);
            way = fmaf(ws, fh.y + fl.y, way);
        }
        __syncthreads();   // done reading A before restage
    }

    // ---- cross-quadrant reduce and store ----
    ((float2*)(smem + PART_OFF))[q * 64 + e2] = make_float2(wax, way);
    __syncthreads();

    if (tid < 64) {
        const float2* p = (const float2*)(smem + PART_OFF);
        float2 r0 = p[tid], r1 = p[64 + tid], r2 = p[128 + tid], r3 = p[192 + tid];
        float2 o = make_float2(r0.x + r1.x + r2.x + r3.x, r0.y + r1.y + r2.y + r3.y);
        *reinterpret_cast<float2*>(out + (size_t)b * ED + tid * 2) = o;
    }
}

extern "C" void kernel_launch(void* const* d_in, const int* in_sizes, int n_in,
                              void* d_out, int out_size)
{
    const float* behav  = (const float*)d_in[0];
    const float* target = (const float*)d_in[1];
    const float* W1     = (const float*)d_in[2];
    const float* b1     = (const float*)d_in[3];
    const float* W2     = (const float*)d_in[4];
    const float* b2     = (const float*)d_in[5];
    float* out = (float*)d_out;

    const int B = in_sizes[1] / ED;   // 2048

    static bool attr_set = false;
    if (!attr_set) {
        cudaFuncSetAttribute(attn_din_kernel,
                             cudaFuncAttributeMaxDynamicSharedMemorySize, (int)SMEM_BYTES);
        attr_set = true;
    }

    attn_din_kernel<<<B, THREADS, SMEM_BYTES>>>(behav, target, W1, b1, W2, b2, out);
}

// round 5
// speedup vs baseline: 1.9515x; 1.3759x over previous
#include <cuda_runtime.h>
#include <cuda_fp16.h>
#include <cstdint>

#define ED   128
#define AD   64
#define THREADS 256
#define ROWB 272u        // padded row stride (136 fp16) -> conflict-free frags

// ---- shared memory layout (bytes) ----
#define A_HI_OFF 0u          // 128 rows x 272 B = 34816
#define A_LO_OFF 34816u
#define W_OFF    69632u      // 64 rows x 272 B = 17408
#define T_OFF    87040u      // 128 f32
#define C_OFF    87552u      // 64 f32
#define W2_OFF   87808u      // 64 f32
#define WARR_OFF 88064u      // 128 f32
#define PART_OFF 88576u      // 256 float2
#define B2_OFF   90624u
#define SMEM_BYTES 90640u

static __device__ __forceinline__ void mma16816(
    float c[4], const uint32_t a[4], uint32_t b0, uint32_t b1)
{
    asm volatile(
        "mma.sync.aligned.m16n8k16.row.col.f32.f16.f16.f32 "
        "{%0,%1,%2,%3}, {%4,%5,%6,%7}, {%8,%9}, {%0,%1,%2,%3};"
        : "+f"(c[0]), "+f"(c[1]), "+f"(c[2]), "+f"(c[3])
        : "r"(a[0]), "r"(a[1]), "r"(a[2]), "r"(a[3]), "r"(b0), "r"(b1));
}

__global__ void __launch_bounds__(THREADS, 2)
attn_din_kernel(const float* __restrict__ behav,
                const float* __restrict__ target,
                const float* __restrict__ W1,
                const float* __restrict__ b1,
                const float* __restrict__ W2,
                const float* __restrict__ b2,
                float* __restrict__ out)
{
    extern __shared__ char smem[];
    const int tid  = threadIdx.x;
    const int wid  = tid >> 5;
    const int lane = tid & 31;
    const int b    = blockIdx.x;

    float* tS  = (float*)(smem + T_OFF);
    float* cS  = (float*)(smem + C_OFF);
    float* w2S = (float*)(smem + W2_OFF);
    float* wAr = (float*)(smem + WARR_OFF);

    // ---- stage small vectors ----
    if (tid < ED) tS[tid]  = target[(size_t)b * ED + tid];
    if (tid < AD) w2S[tid] = W2[tid];
    if (tid == 0) *((float*)(smem + B2_OFF)) = b2[0];
    __syncthreads();   // tS ready

    // ---- build per-batch weight W_b[a][k] = Wx + Wd + t[k]*Wm (single fp16), once ----
    for (int idx = tid; idx < ED * AD; idx += THREADS) {
        int k = idx >> 6, a = idx & 63;
        float w = W1[k * AD + a] + W1[(384 + k) * AD + a] + tS[k] * W1[(256 + k) * AD + a];
        uint32_t off = (uint32_t)a * ROWB + (uint32_t)k * 2u;
        *reinterpret_cast<__half*>(smem + W_OFF + off) = __float2half_rn(w);
    }

    // ---- c[a] partials: c = b1 + t @ (W_t - W_d), 4 k-quadrants ----
    {
        int a = tid & 63, q = tid >> 6;
        float acc = 0.f;
        for (int kk = 0; kk < 32; kk++) {
            int k = q * 32 + kk;
            acc += tS[k] * (W1[(128 + k) * AD + a] - W1[(384 + k) * AD + a]);
        }
        ((float*)(smem + PART_OFF))[q * 64 + a] = acc;
    }
    __syncthreads();

    if (tid < AD) {
        const float* p = (const float*)(smem + PART_OFF);
        cS[tid] = b1[tid] + p[tid] + p[64 + tid] + p[128 + tid] + p[192 + tid];
    }
    // cS consumed only after the next __syncthreads (inside half loop).

    const int g  = lane >> 2;          // fragment row/col group
    const int t2 = (lane & 3) * 2;     // k sub-offset

    float wax = 0.f, way = 0.f;        // persistent weighted-sum accumulators
    const int e2 = tid & 63, q = tid >> 6;

    for (int half = 0; half < 2; half++) {
        const int rows_real = half ? 72 : 128;

        // ---- stage A rows: hi/lo fp16 split (no zero padding; guards mask stale) ----
        {
            const float4* bp = (const float4*)(behav
                + ((size_t)b * 200 + (size_t)half * 128) * ED);
            for (int r = wid; r < rows_real; r += 8) {
                float4 v = bp[r * (ED / 4) + lane];
                __half2 h01 = __floats2half2_rn(v.x, v.y);
                __half2 h23 = __floats2half2_rn(v.z, v.w);
                float2 f01 = __half22float2(h01);
                float2 f23 = __half22float2(h23);
                __half2 l01 = __floats2half2_rn(v.x - f01.x, v.y - f01.y);
                __half2 l23 = __floats2half2_rn(v.z - f23.x, v.w - f23.y);
                uint32_t off = (uint32_t)r * ROWB + (uint32_t)lane * 8u;
                *reinterpret_cast<uint2*>(smem + A_HI_OFF + off) =
                    make_uint2(*(uint32_t*)&h01, *(uint32_t*)&h23);
                *reinterpret_cast<uint2*>(smem + A_LO_OFF + off) =
                    make_uint2(*(uint32_t*)&l01, *(uint32_t*)&l23);
            }
        }
        __syncthreads();   // A ready (and cS on half 0)

        // ---- GEMM: warp w -> rows [16w,16w+16) x [64]; 2 passes share B frags ----
        float acc[8][4];
#pragma unroll
        for (int n = 0; n < 8; n++)
#pragma unroll
            for (int i = 0; i < 4; i++) acc[n][i] = 0.f;

        if (wid * 16 < rows_real) {
#pragma unroll
            for (int ks = 0; ks < 8; ks++) {
                const uint32_t kb = (uint32_t)(ks * 16 + t2) * 2u;
                const uint32_t rowb = (uint32_t)(wid * 16 + g) * ROWB + kb;
                const char* bh = smem + A_HI_OFF + rowb;
                const char* bl = smem + A_LO_OFF + rowb;
                uint32_t ah[4], al[4];
                ah[0] = *(const uint32_t*)(bh);
                ah[1] = *(const uint32_t*)(bh + 8 * ROWB);
                ah[2] = *(const uint32_t*)(bh + 16);
                ah[3] = *(const uint32_t*)(bh + 8 * ROWB + 16);
                al[0] = *(const uint32_t*)(bl);
                al[1] = *(const uint32_t*)(bl + 8 * ROWB);
                al[2] = *(const uint32_t*)(bl + 16);
                al[3] = *(const uint32_t*)(bl + 8 * ROWB + 16);
#pragma unroll
                for (int n = 0; n < 8; n++) {
                    const char* wb = smem + W_OFF + (uint32_t)(n * 8 + g) * ROWB + kb;
                    uint32_t b0  = *(const uint32_t*)(wb);
                    uint32_t b1r = *(const uint32_t*)(wb + 16);
                    mma16816(acc[n], ah, b0, b1r);
                    mma16816(acc[n], al, b0, b1r);
                }
            }
        }

        // ---- epilogue: z = b2 + sum_a relu(D+c)*W2 ; wAr = sigmoid(z) (0 if padded) ----
        {
            const float b2v = *((const float*)(smem + B2_OFF));
#pragma unroll
            for (int h = 0; h < 2; h++) {
                float z = 0.f;
#pragma unroll
                for (int n = 0; n < 8; n++) {
                    int col = n * 8 + t2;
                    float h0 = fmaxf(acc[n][2 * h]     + cS[col],     0.f);
                    float h1 = fmaxf(acc[n][2 * h + 1] + cS[col + 1], 0.f);
                    z = fmaf(h0, w2S[col], z);
                    z = fmaf(h1, w2S[col + 1], z);
                }
                z += __shfl_xor_sync(0xFFFFFFFFu, z, 1);
                z += __shfl_xor_sync(0xFFFFFFFFu, z, 2);
                int s = wid * 16 + h * 8 + g;
                if ((lane & 3) == 0) {
                    float wgt = (s < rows_real) ? (1.f / (1.f + __expf(-(z + b2v)))) : 0.f;
                    wAr[s] = wgt;
                }
            }
        }
        __syncthreads();   // wAr ready

        // ---- weighted partial: accumulate w[s]*x[s][e] into registers ----
#pragma unroll 4
        for (int i = 0; i < 32; i++) {
            int s = q * 32 + i;
            uint32_t off = (uint32_t)s * ROWB + (uint32_t)e2 * 4u;
            __half2 h2 = *reinterpret_cast<const __half2*>(smem + A_HI_OFF + off);
            __half2 l2 = *reinterpret_cast<const __half2*>(smem + A_LO_OFF + off);
            float2 fh = __half22float2(h2);
            float2 fl = __half22float2(l2);
            float ws = wAr[s];
            wax = fmaf(ws, fh.x + fl.x, wax);
            way = fmaf(ws, fh.y + fl.y, way);
        }
        __syncthreads();   // done reading A before restage
    }

    // ---- cross-quadrant reduce and store ----
    ((float2*)(smem + PART_OFF))[q * 64 + e2] = make_float2(wax, way);
    __syncthreads();

    if (tid < 64) {
        const float2* p = (const float2*)(smem + PART_OFF);
        float2 r0 = p[tid], r1 = p[64 + tid], r2 = p[128 + tid], r3 = p[192 + tid];
        float2 o = make_float2(r0.x + r1.x + r2.x + r3.x, r0.y + r1.y + r2.y + r3.y);
        *reinterpret_cast<float2*>(out + (size_t)b * ED + tid * 2) = o;
    }
}

extern "C" void kernel_launch(void* const* d_in, const int* in_sizes, int n_in,
                              void* d_out, int out_size)
{
    const float* behav  = (const float*)d_in[0];
    const float* target = (const float*)d_in[1];
    const float* W1     = (const float*)d_in[2];
    const float* b1     = (const float*)d_in[3];
    const float* W2     = (const float*)d_in[4];
    const float* b2     = (const float*)d_in[5];
    float* out = (float*)d_out;

    const int B = in_sizes[1] / ED;   // 2048

    static bool attr_set = false;
    if (!attr_set) {
        cudaFuncSetAttribute(attn_din_kernel,
                             cudaFuncAttributeMaxDynamicSharedMemorySize, (int)SMEM_BYTES);
        attr_set = true;
    }

    attn_din_kernel<<<B, THREADS, SMEM_BYTES>>>(behav, target, W1, b1, W2, b2, out);
}

// round 6
// speedup vs baseline: 2.6588x; 1.3624x over previous
#include <cuda_runtime.h>
#include <cuda_fp16.h>
#include <cstdint>

#define ED   128
#define AD   64
#define THREADS 256
#define ROWB 272u        // padded row stride (136 fp16) -> conflict-free frags

// ---- shared memory layout (bytes) ----
#define A_OFF    0u          // 128 rows x 272 B = 34816
#define W_OFF    34816u      // 64 rows x 272 B = 17408
#define T_OFF    52224u      // 128 f32
#define C_OFF    52736u      // 64 f32
#define W2_OFF   52992u      // 64 f32
#define WARR_OFF 53248u      // 128 f32
#define PART_OFF 53760u      // 256 float2
#define B2_OFF   55808u
#define SMEM_BYTES 55824u

static __device__ __forceinline__ void mma16816(
    float c[4], const uint32_t a[4], uint32_t b0, uint32_t b1)
{
    asm volatile(
        "mma.sync.aligned.m16n8k16.row.col.f32.f16.f16.f32 "
        "{%0,%1,%2,%3}, {%4,%5,%6,%7}, {%8,%9}, {%0,%1,%2,%3};"
        : "+f"(c[0]), "+f"(c[1]), "+f"(c[2]), "+f"(c[3])
        : "r"(a[0]), "r"(a[1]), "r"(a[2]), "r"(a[3]), "r"(b0), "r"(b1));
}

__global__ void __launch_bounds__(THREADS, 3)
attn_din_kernel(const float* __restrict__ behav,
                const float* __restrict__ target,
                const float* __restrict__ W1,
                const float* __restrict__ b1,
                const float* __restrict__ W2,
                const float* __restrict__ b2,
                float* __restrict__ out)
{
    extern __shared__ char smem[];
    const int tid  = threadIdx.x;
    const int wid  = tid >> 5;
    const int lane = tid & 31;
    const int b    = blockIdx.x;

    float* tS  = (float*)(smem + T_OFF);
    float* cS  = (float*)(smem + C_OFF);
    float* w2S = (float*)(smem + W2_OFF);
    float* wAr = (float*)(smem + WARR_OFF);

    // ---- stage small vectors ----
    if (tid < ED) tS[tid]  = target[(size_t)b * ED + tid];
    if (tid < AD) w2S[tid] = W2[tid];
    if (tid == 0) *((float*)(smem + B2_OFF)) = b2[0];
    __syncthreads();   // tS ready

    // ---- build per-batch weight W_b[a][k] = Wx + Wd + t[k]*Wm (fp16), once ----
    for (int idx = tid; idx < ED * AD; idx += THREADS) {
        int k = idx >> 6, a = idx & 63;
        float w = W1[k * AD + a] + W1[(384 + k) * AD + a] + tS[k] * W1[(256 + k) * AD + a];
        uint32_t off = (uint32_t)a * ROWB + (uint32_t)k * 2u;
        *reinterpret_cast<__half*>(smem + W_OFF + off) = __float2half_rn(w);
    }

    // ---- c[a] partials: c = b1 + t @ (W_t - W_d), 4 k-quadrants ----
    {
        int a = tid & 63, q = tid >> 6;
        float acc = 0.f;
        for (int kk = 0; kk < 32; kk++) {
            int k = q * 32 + kk;
            acc += tS[k] * (W1[(128 + k) * AD + a] - W1[(384 + k) * AD + a]);
        }
        ((float*)(smem + PART_OFF))[q * 64 + a] = acc;
    }
    __syncthreads();

    if (tid < AD) {
        const float* p = (const float*)(smem + PART_OFF);
        cS[tid] = b1[tid] + p[tid] + p[64 + tid] + p[128 + tid] + p[192 + tid];
    }
    // cS consumed only after the next __syncthreads (inside half loop).

    const int g  = lane >> 2;          // fragment row/col group
    const int t2 = (lane & 3) * 2;     // k sub-offset

    float wax = 0.f, way = 0.f;        // persistent weighted-sum accumulators
    const int e2 = tid & 63, q = tid >> 6;

    for (int half = 0; half < 2; half++) {
        const int rows_real = half ? 72 : 128;

        // ---- stage A rows: single fp16 (no padding; guards mask stale rows) ----
        {
            const float4* bp = (const float4*)(behav
                + ((size_t)b * 200 + (size_t)half * 128) * ED);
            for (int r = wid; r < rows_real; r += 8) {
                float4 v = bp[r * (ED / 4) + lane];
                __half2 h01 = __floats2half2_rn(v.x, v.y);
                __half2 h23 = __floats2half2_rn(v.z, v.w);
                uint32_t off = (uint32_t)r * ROWB + (uint32_t)lane * 8u;
                *reinterpret_cast<uint2*>(smem + A_OFF + off) =
                    make_uint2(*(uint32_t*)&h01, *(uint32_t*)&h23);
            }
        }
        __syncthreads();   // A ready (and cS on half 0)

        // ---- GEMM: warp w -> rows [16w,16w+16) x [64]; single fp16 pass ----
        float acc[8][4];
#pragma unroll
        for (int n = 0; n < 8; n++)
#pragma unroll
            for (int i = 0; i < 4; i++) acc[n][i] = 0.f;

        if (wid * 16 < rows_real) {
#pragma unroll
            for (int ks = 0; ks < 8; ks++) {
                const uint32_t kb = (uint32_t)(ks * 16 + t2) * 2u;
                const char* base = smem + A_OFF + (uint32_t)(wid * 16 + g) * ROWB + kb;
                uint32_t a[4];
                a[0] = *(const uint32_t*)(base);
                a[1] = *(const uint32_t*)(base + 8 * ROWB);
                a[2] = *(const uint32_t*)(base + 16);
                a[3] = *(const uint32_t*)(base + 8 * ROWB + 16);
#pragma unroll
                for (int n = 0; n < 8; n++) {
                    const char* wb = smem + W_OFF + (uint32_t)(n * 8 + g) * ROWB + kb;
                    uint32_t b0  = *(const uint32_t*)(wb);
                    uint32_t b1r = *(const uint32_t*)(wb + 16);
                    mma16816(acc[n], a, b0, b1r);
                }
            }
        }

        // ---- epilogue: z = b2 + sum_a relu(D+c)*W2 ; wAr = sigmoid(z) (0 if padded) ----
        {
            const float b2v = *((const float*)(smem + B2_OFF));
#pragma unroll
            for (int h = 0; h < 2; h++) {
                float z = 0.f;
#pragma unroll
                for (int n = 0; n < 8; n++) {
                    int col = n * 8 + t2;
                    float h0 = fmaxf(acc[n][2 * h]     + cS[col],     0.f);
                    float h1 = fmaxf(acc[n][2 * h + 1] + cS[col + 1], 0.f);
                    z = fmaf(h0, w2S[col], z);
                    z = fmaf(h1, w2S[col + 1], z);
                }
                z += __shfl_xor_sync(0xFFFFFFFFu, z, 1);
                z += __shfl_xor_sync(0xFFFFFFFFu, z, 2);
                int s = wid * 16 + h * 8 + g;
                if ((lane & 3) == 0) {
                    float wgt = (s < rows_real) ? (1.f / (1.f + __expf(-(z + b2v)))) : 0.f;
                    wAr[s] = wgt;
                }
            }
        }
        __syncthreads();   // wAr ready

        // ---- weighted partial: accumulate w[s]*x[s][e] into registers ----
#pragma unroll 4
        for (int i = 0; i < 32; i++) {
            int s = q * 32 + i;
            uint32_t off = (uint32_t)s * ROWB + (uint32_t)e2 * 4u;
            __half2 h2 = *reinterpret_cast<const __half2*>(smem + A_OFF + off);
            float2 fh = __half22float2(h2);
            float ws = wAr[s];
            wax = fmaf(ws, fh.x, wax);
            way = fmaf(ws, fh.y, way);
        }
        __syncthreads();   // done reading A before restage
    }

    // ---- cross-quadrant reduce and store ----
    ((float2*)(smem + PART_OFF))[q * 64 + e2] = make_float2(wax, way);
    __syncthreads();

    if (tid < 64) {
        const float2* p = (const float2*)(smem + PART_OFF);
        float2 r0 = p[tid], r1 = p[64 + tid], r2 = p[128 + tid], r3 = p[192 + tid];
        float2 o = make_float2(r0.x + r1.x + r2.x + r3.x, r0.y + r1.y + r2.y + r3.y);
        *reinterpret_cast<float2*>(out + (size_t)b * ED + tid * 2) = o;
    }
}

extern "C" void kernel_launch(void* const* d_in, const int* in_sizes, int n_in,
                              void* d_out, int out_size)
{
    const float* behav  = (const float*)d_in[0];
    const float* target = (const float*)d_in[1];
    const float* W1     = (const float*)d_in[2];
    const float* b1     = (const float*)d_in[3];
    const float* W2     = (const float*)d_in[4];
    const float* b2     = (const float*)d_in[5];
    float* out = (float*)d_out;

    const int B = in_sizes[1] / ED;   // 2048

    static bool attr_set = false;
    if (!attr_set) {
        cudaFuncSetAttribute(attn_din_kernel,
                             cudaFuncAttributeMaxDynamicSharedMemorySize, (int)SMEM_BYTES);
        attr_set = true;
    }

    attn_din_kernel<<<B, THREADS, SMEM_BYTES>>>(behav, target, W1, b1, W2, b2, out);
}